// round 11
// baseline (speedup 1.0000x reference)
#include <cuda_runtime.h>
#include <cuda_bf16.h>
#include <stdint.h>
#include <math.h>

#define THREADS 256
typedef unsigned short ushort_t;

// ---------------- fp32 intermediates ----------------
__device__ float g_w0[75497472];      // (8,576,128,128)
__device__ float g_pool2[37748736];   // (8,288,128,128) x2 half fp32 (maxpool source)
__device__ float g_X1[37748736];      // (8,288,128,128)
__device__ float g_weight[18874368];  // (8,576,64,64)
__device__ float g_f[18874368];       // (8,576,64,64)
__device__ float g_tw[16384];
__device__ float g_ct[128];
__device__ float g_st[128];

// ---------------- packed bf16 hi/lo (2 k's per uint32, low16 = even k) ----------------
__device__ uint32_t g_spdPh[16777216], g_spdPl[16777216];   // B: (8,128 k2,16384)
__device__ uint32_t g_poolAh[18874368], g_poolAl[18874368]; // A rows: (8*288*128, 64 words)
__device__ uint32_t g_catPh[18874368],  g_catPl[18874368];  // B: (8,576 k2,4096)
__device__ uint32_t g_mpPh[4718592],    g_mpPl[4718592];    // B: (8,144 k2,4096)
__device__ uint32_t g_colPh[37748736],  g_colPl[37748736];  // B: (8,1152 k2,4096)
__device__ uint32_t g_wdPh[9437184],    g_wdPl[9437184];    // B: (8,288 k2,4096)
__device__ uint32_t g_twBh[8192],       g_twBl[8192];       // B: (64 k2,128)
__device__ uint32_t g_wgwh[73728],  g_wgwl[73728];          // A 576x128w
__device__ uint32_t g_wfmh[165888], g_wfml[165888];         // A 288x576w
__device__ uint32_t g_wcvh[41472],  g_wcvl[41472];          // A 288x144w
__device__ uint32_t g_wgfh[663552], g_wgfl[663552];         // A 576x1152w
__device__ uint32_t g_wouth[36864], g_woutl[36864];         // A 128x288w

__device__ __forceinline__ void split2(float a, float b, uint32_t& hw, uint32_t& lw) {
    __nv_bfloat16 ah = __float2bfloat16(a), bh = __float2bfloat16(b);
    __nv_bfloat16 al = __float2bfloat16(a - __bfloat162float(ah));
    __nv_bfloat16 bl = __float2bfloat16(b - __bfloat162float(bh));
    hw = (uint32_t)*(ushort_t*)&ah | ((uint32_t)*(ushort_t*)&bh << 16);
    lw = (uint32_t)*(ushort_t*)&al | ((uint32_t)*(ushort_t*)&bl << 16);
}

__global__ void init_tw_kernel() {
    int i = blockIdx.x * blockDim.x + threadIdx.x;
    const double TWO_PI = 6.283185307179586476925286766559;
    if (i < 16384) {
        int q = i >> 7, v = i & 127;
        if (v < 64)
            g_tw[i] = (float)cos(TWO_PI * (double)((q * v) & 127) / 128.0);
        else
            g_tw[i] = (float)(-sin(TWO_PI * (double)((q * (v - 64)) & 127) / 128.0));
    }
    if (i < 128) {
        g_ct[i] = (float)cos(TWO_PI * (double)i / 128.0);
        g_st[i] = (float)sin(TWO_PI * (double)i / 128.0);
    }
}

__global__ void twpack_kernel() {
    int i = blockIdx.x * blockDim.x + threadIdx.x;
    if (i >= 8192) return;
    int k2 = i >> 7, v = i & 127;
    split2(g_tw[(2 * k2) * 128 + v], g_tw[(2 * k2 + 1) * 128 + v], g_twBh[i], g_twBl[i]);
}

__global__ void wsplit_kernel(const float* __restrict__ W, uint32_t* __restrict__ Wh,
                              uint32_t* __restrict__ Wl, int nwords) {
    int i = blockIdx.x * THREADS + threadIdx.x;
    if (i >= nwords) return;
    split2(W[2 * i], W[2 * i + 1], Wh[i], Wl[i]);
}

// space-to-depth: channel pair per thread -> full-word packed stores, no fp32 copy
__global__ void spd_kernel(const float* __restrict__ x) {
    int i = blockIdx.x * THREADS + threadIdx.x;
    if (i >= 16777216) return;
    int n = i & 16383, s2 = (i >> 14) & 127, b = i >> 21;
    int q = n & 127, p = n >> 7;
    int s0 = s2 << 1;
    int quad = s0 >> 6, c = s0 & 63;
    int r  = 2 * p + (quad & 1);
    int cc = 2 * q + (quad >> 1);
    const float* xp = x + ((size_t)(b * 64 + c) * 256 + r) * 256 + cc;
    float v0 = xp[0];
    float v1 = xp[65536];          // channel c+1 (same quad: s0 even => c <= 62)
    uint32_t h, l;
    split2(v0, v1, h, l);
    size_t w = ((size_t)(b * 128 + s2) << 14) + n;
    g_spdPh[w] = h; g_spdPl[w] = l;
}

__global__ void avgpool_kernel() {
    int i = blockIdx.x * THREADS + threadIdx.x;
    if (i >= 18874368) return;
    int q4 = (i & 31) << 2;
    int p  = (i >> 5) & 127;
    int cb = i >> 12;
    int ch = cb % 576, b = cb / 576;
    float4 o = make_float4(0.f, 0.f, 0.f, 0.f);
    if (p < 127) {
        const float* s = g_w0 + ((size_t)cb << 14);
        int ofs = (p << 7) + q4;
        float4 a = *(const float4*)(s + ofs);
        float4 bb = *(const float4*)(s + ofs + 128);
        o.x = 0.25f * (a.x + a.y + bb.x + bb.y);
        o.y = 0.25f * (a.y + a.z + bb.y + bb.z);
        o.z = 0.25f * (a.z + a.w + bb.z + bb.w);
        if (q4 < 124) {
            float a4 = s[ofs + 4], b4 = s[ofs + 132];
            o.w = 0.25f * (a.w + a4 + bb.w + b4);
        }
    }
    if (ch < 288) {
        uint32_t h0, l0, h1, l1;
        split2(o.x, o.y, h0, l0);
        split2(o.z, o.w, h1, l1);
        size_t wb = ((size_t)(b * 288 + ch) << 13) + (p << 6) + (q4 >> 1);
        g_poolAh[wb] = h0; g_poolAh[wb + 1] = h1;
        g_poolAl[wb] = l0; g_poolAl[wb + 1] = l1;
    } else {
        *(float4*)(g_pool2 + ((size_t)(b * 288 + ch - 288) << 14) + (p << 7) + q4) = o;
    }
}

// maxpool: channel pair per thread -> full-word stores
__global__ void maxpool_kernel() {
    int i = blockIdx.x * THREADS + threadIdx.x;
    if (i >= 4718592) return;
    int n = i & 4095;
    int v = n & 63, u = n >> 6;
    int cb = i >> 12;
    int c2 = cb % 144, b = cb / 144;
    const float* sA = g_pool2 + ((size_t)(b * 288 + 2 * c2) << 14);
    const float* sB = sA + 16384;
    int r0 = max(2 * u - 1, 0), r1 = min(2 * u + 1, 126);
    int q0 = max(2 * v - 1, 0), q1 = min(2 * v + 1, 126);
    float m0 = -3.4e38f, m1 = -3.4e38f;
    for (int r = r0; r <= r1; r++)
        for (int cc = q0; cc <= q1; cc++) {
            int o = (r << 7) + cc;
            m0 = fmaxf(m0, sA[o]);
            m1 = fmaxf(m1, sB[o]);
        }
    uint32_t h, l;
    split2(m0, m1, h, l);
    size_t w = ((size_t)(b * 144 + c2) << 12) + n;
    g_mpPh[w] = h; g_mpPl[w] = l;
}

// im2col: k pair per thread, gathers ushorts from packed spd, full-word stores
__global__ void im2col_kernel() {
    int i = blockIdx.x * THREADS + threadIdx.x;
    if (i >= 37748736) return;
    int n = i & 4095;
    int v = n & 63, u = n >> 6;
    int kb = i >> 12;
    int k2 = kb % 1152, b = kb / 1152;
    const ushort_t* sph = (const ushort_t*)g_spdPh;
    const ushort_t* spl = (const ushort_t*)g_spdPl;
    uint32_t hw = 0, lw = 0;
    #pragma unroll
    for (int e = 0; e < 2; e++) {
        int k = 2 * k2 + e;
        int ic = k / 9, t = k - ic * 9;
        int di = t / 3, dj = t - di * 3;
        int r  = 2 * u + di - 1;
        int cc = 2 * v + dj - 1;
        ushort_t hv = 0, lv = 0;
        if ((unsigned)r < 128u && (unsigned)cc < 128u) {
            size_t idx = ((((size_t)(b * 128 + (ic >> 1)) << 14) + (r << 7) + cc) << 1) + (ic & 1);
            hv = sph[idx]; lv = spl[idx];
        }
        hw |= (uint32_t)hv << (16 * e);
        lw |= (uint32_t)lv << (16 * e);
    }
    size_t w = ((size_t)(b * 1152 + k2) << 12) + n;
    g_colPh[w] = hw; g_colPl[w] = lw;
}

// column FFT radix-4, float2 LDS, TWO channels per block, full-word packed stores
#define FFT_SMEM ((8192 + 128) * 8)
__global__ __launch_bounds__(256) void fft_col_kernel() {
    extern __shared__ float2 ds[];
    float2* Xs0 = ds;            // [128][32] ch0 (re,im)
    float2* Xs1 = ds + 4096;     // ch1
    float2* tws = ds + 8192;     // [128] (cos,sin)
    int blk = blockIdx.x;        // b*144 + j
    int b = blk / 144, j = blk % 144;
    int tid = threadIdx.x;
    if (tid < 128) tws[tid] = make_float2(g_ct[tid], g_st[tid]);
    const float* X1a = g_X1 + (size_t)(b * 288 + 2 * j) * 16384;
    const float* X1b = X1a + 16384;
    size_t wLRe = ((size_t)(b * 576) + j) << 12;
    size_t wLIm = wLRe + ((size_t)144 << 12);
    size_t wHRe = wLRe + ((size_t)288 << 12);
    size_t wHIm = wLRe + ((size_t)432 << 12);
    for (int half = 0; half < 2; half++) {
        int v0 = half << 5;
        __syncthreads();
        for (int e = tid; e < 4096; e += 256) {
            int p = e >> 5, v = e & 31;
            Xs0[(p << 5) + v] = make_float2(X1a[(p << 7) + v0 + v], X1a[(p << 7) + 64 + v0 + v]);
            Xs1[(p << 5) + v] = make_float2(X1b[(p << 7) + v0 + v], X1b[(p << 7) + 64 + v0 + v]);
        }
        __syncthreads();
        for (int r = 0; r < 4; r++) {
            int item = (r << 8) + tid;
            int u = item >> 5, v = item & 31;
            float a0r=0.f,a0i=0.f,a1r=0.f,a1i=0.f,a2r=0.f,a2i=0.f,a3r=0.f,a3i=0.f;
            float b0r=0.f,b0i=0.f,b1r=0.f,b1i=0.f,b2r=0.f,b2i=0.f,b3r=0.f,b3i=0.f;
            int u1 = u, u2 = (2 * u) & 127, u3 = (3 * u) & 127, u4 = (4 * u) & 127;
            int idx = 0;
            #pragma unroll 4
            for (int p = 0; p < 128; p += 4) {
                {
                    float2 t = tws[idx];
                    float2 xa = Xs0[(p << 5) + v], xb = Xs1[(p << 5) + v];
                    a0r = fmaf(xa.x, t.x, a0r); a0r = fmaf(xa.y, t.y, a0r);
                    a0i = fmaf(xa.y, t.x, a0i); a0i = fmaf(-xa.x, t.y, a0i);
                    b0r = fmaf(xb.x, t.x, b0r); b0r = fmaf(xb.y, t.y, b0r);
                    b0i = fmaf(xb.y, t.x, b0i); b0i = fmaf(-xb.x, t.y, b0i);
                }
                {
                    int id = (idx + u1) & 127;
                    float2 t = tws[id];
                    float2 xa = Xs0[((p + 1) << 5) + v], xb = Xs1[((p + 1) << 5) + v];
                    a1r = fmaf(xa.x, t.x, a1r); a1r = fmaf(xa.y, t.y, a1r);
                    a1i = fmaf(xa.y, t.x, a1i); a1i = fmaf(-xa.x, t.y, a1i);
                    b1r = fmaf(xb.x, t.x, b1r); b1r = fmaf(xb.y, t.y, b1r);
                    b1i = fmaf(xb.y, t.x, b1i); b1i = fmaf(-xb.x, t.y, b1i);
                }
                {
                    int id = (idx + u2) & 127;
                    float2 t = tws[id];
                    float2 xa = Xs0[((p + 2) << 5) + v], xb = Xs1[((p + 2) << 5) + v];
                    a2r = fmaf(xa.x, t.x, a2r); a2r = fmaf(xa.y, t.y, a2r);
                    a2i = fmaf(xa.y, t.x, a2i); a2i = fmaf(-xa.x, t.y, a2i);
                    b2r = fmaf(xb.x, t.x, b2r); b2r = fmaf(xb.y, t.y, b2r);
                    b2i = fmaf(xb.y, t.x, b2i); b2i = fmaf(-xb.x, t.y, b2i);
                }
                {
                    int id = (idx + u3) & 127;
                    float2 t = tws[id];
                    float2 xa = Xs0[((p + 3) << 5) + v], xb = Xs1[((p + 3) << 5) + v];
                    a3r = fmaf(xa.x, t.x, a3r); a3r = fmaf(xa.y, t.y, a3r);
                    a3i = fmaf(xa.y, t.x, a3i); a3i = fmaf(-xa.x, t.y, a3i);
                    b3r = fmaf(xb.x, t.x, b3r); b3r = fmaf(xb.y, t.y, b3r);
                    b3i = fmaf(xb.y, t.x, b3i); b3i = fmaf(-xb.x, t.y, b3i);
                }
                idx = (idx + u4) & 127;
            }
            // butterflies
            float ArA = a0r + a2r, AiA = a0i + a2i, ArB = a0r - a2r, AiB = a0i - a2i;
            float ArC = a1r + a3r, AiC = a1i + a3i, ArD = a1r - a3r, AiD = a1i - a3i;
            float BrA = b0r + b2r, BiA = b0i + b2i, BrB = b0r - b2r, BiB = b0i - b2i;
            float BrC = b1r + b3r, BiC = b1i + b3i, BrD = b1r - b3r, BiD = b1i - b3i;
            int vv = v0 + v;
            size_t off_u   = (size_t)((u << 6) + vv);
            size_t off_u32 = (size_t)(((u + 32) << 6) + vv);
            uint32_t h, l;
            split2(ArA + ArC, BrA + BrC, h, l); g_catPh[wLRe + off_u]   = h; g_catPl[wLRe + off_u]   = l;
            split2(AiA + AiC, BiA + BiC, h, l); g_catPh[wLIm + off_u]   = h; g_catPl[wLIm + off_u]   = l;
            split2(ArB + AiD, BrB + BiD, h, l); g_catPh[wLRe + off_u32] = h; g_catPl[wLRe + off_u32] = l;
            split2(AiB - ArD, BiB - BrD, h, l); g_catPh[wLIm + off_u32] = h; g_catPl[wLIm + off_u32] = l;
            split2(ArA - ArC, BrA - BrC, h, l); g_catPh[wHRe + off_u]   = h; g_catPl[wHRe + off_u]   = l;
            split2(AiA - AiC, BiA - BiC, h, l); g_catPh[wHIm + off_u]   = h; g_catPl[wHIm + off_u]   = l;
            split2(ArB - AiD, BrB - BiD, h, l); g_catPh[wHRe + off_u32] = h; g_catPl[wHRe + off_u32] = l;
            split2(AiB + ArD, BiB + BrD, h, l); g_catPh[wHIm + off_u32] = h; g_catPl[wHIm + off_u32] = l;
        }
    }
}

// softmax+gate: channel pair per thread -> full-word stores
__global__ void softmax_wd_kernel() {
    int i = blockIdx.x * THREADS + threadIdx.x;
    if (i >= 1048576) return;
    int n = i & 4095;
    int jb = i >> 12;
    int j = jb & 31, b = jb >> 5;
    float flat[18];
    #pragma unroll
    for (int e = 0; e < 2; e++) {
        int c = 2 * j + e;
        size_t base = (size_t)(b * 576 + c * 9) * 4096 + n;
        float w[9];
        float mx = -3.4e38f;
        #pragma unroll
        for (int t = 0; t < 9; t++) { w[t] = g_weight[base + t * 4096]; mx = fmaxf(mx, w[t]); }
        float sum = 0.f;
        #pragma unroll
        for (int t = 0; t < 9; t++) { w[t] = expf(w[t] - mx); sum += w[t]; }
        float inv = 1.f / sum;
        #pragma unroll
        for (int t = 0; t < 9; t++)
            flat[e * 9 + t] = g_f[base + t * 4096] * w[t] * inv;
    }
    #pragma unroll
    for (int w = 0; w < 9; w++) {
        uint32_t h, l;
        split2(flat[2 * w], flat[2 * w + 1], h, l);
        size_t idx = ((size_t)(b * 288 + 9 * j + w) << 12) + n;
        g_wdPh[idx] = h; g_wdPl[idx] = l;
    }
}

// ---------------- tensor-core GEMM, pre-split packed bf16, 3-stage cp.async ----------------
#define MMA_BF16(d, a, b0_, b1_) \
    asm volatile("mma.sync.aligned.m16n8k16.row.col.f32.bf16.bf16.f32 " \
        "{%0,%1,%2,%3},{%4,%5,%6,%7},{%8,%9},{%0,%1,%2,%3};" \
        : "+f"(d[0]), "+f"(d[1]), "+f"(d[2]), "+f"(d[3]) \
        : "r"(a[0]), "r"(a[1]), "r"(a[2]), "r"(a[3]), "r"(b0_), "r"(b1_))

#define CPA(dst, src, sz) asm volatile("cp.async.cg.shared.global [%0], [%1], 16, %2;" \
        :: "r"(dst), "l"(src), "r"(sz))
#define CPC() asm volatile("cp.async.commit_group;")
#define CPW(n) asm volatile("cp.async.wait_group %0;" :: "n"(n))

__device__ __forceinline__ uint32_t smaddr(const void* p) {
    return (uint32_t)__cvta_generic_to_shared(p);
}

#define GSM_BYTES 62976
__global__ __launch_bounds__(256, 2) void bgemm_kernel(
    const uint32_t* __restrict__ Ah, const uint32_t* __restrict__ Al,
    const uint32_t* __restrict__ Bh, const uint32_t* __restrict__ Bl,
    float* __restrict__ C, int M, int N, int K,
    long long sA, long long sB, long long sC,
    const float* __restrict__ G1, const float* __restrict__ Bi1,
    const float* __restrict__ G2, const float* __restrict__ Bi2, int mode)
{
    extern __shared__ uint32_t sm[];
    uint32_t* sAh = sm;              // [3][1536]
    uint32_t* sAl = sm + 4608;       // [3][1536]
    uint32_t* sBh = sm + 9216;       // [3][1088]
    uint32_t* sBl = sm + 12480;      // [3][1088]

    int tid = threadIdx.x;
    int bn0 = blockIdx.x << 7, bm0 = blockIdx.y << 7;
    int Kw = K >> 1;
    Ah += (long long)blockIdx.z * sA;  Al += (long long)blockIdx.z * sA;
    Bh += (long long)blockIdx.z * sB;  Bl += (long long)blockIdx.z * sB;
    C  += (long long)blockIdx.z * sC;

    int aRow = tid >> 1, wofs = (tid & 1) << 2;
    bool aOk = (bm0 + aRow) < M;
    uint32_t szA = aOk ? 16u : 0u;
    const uint32_t* ApH = Ah + (long long)(aOk ? (bm0 + aRow) : 0) * Kw + wofs;
    const uint32_t* ApL = Al + (long long)(aOk ? (bm0 + aRow) : 0) * Kw + wofs;
    int bK2 = tid >> 5, bN0 = (tid & 31) << 2;
    const uint32_t* BpH = Bh + (long long)bK2 * N + bn0 + bN0;
    const uint32_t* BpL = Bl + (long long)bK2 * N + bn0 + bN0;

    uint32_t dA = (uint32_t)(aRow * 12 + wofs);
    uint32_t dB = (uint32_t)(bK2 * 136 + bN0);
    uint32_t bAh = smaddr(sAh), bAl = smaddr(sAl);
    uint32_t bBh = smaddr(sBh), bBl = smaddr(sBl);

    int wid = tid >> 5, lane = tid & 31;
    int wm = (wid >> 2) << 6, wn = (wid & 3) << 5;
    int g = lane >> 2, tg = lane & 3;

    float acc[4][4][4];
    #pragma unroll
    for (int i = 0; i < 4; i++)
        #pragma unroll
        for (int j = 0; j < 4; j++)
            #pragma unroll
            for (int r = 0; r < 4; r++) acc[i][j][r] = 0.f;

    int nstage = K >> 4;

    #pragma unroll
    for (int t = 0; t < 2; t++) {
        if (t < nstage) {
            long long kw = (long long)t << 3;
            uint32_t ao = t * 6144, bo = t * 4352;
            CPA(bAh + ao + dA * 4, ApH + kw, szA);
            CPA(bAl + ao + dA * 4, ApL + kw, szA);
            CPA(bBh + bo + dB * 4, BpH + kw * N, 16);
            CPA(bBl + bo + dB * 4, BpL + kw * N, 16);
            CPC();
        }
    }

    for (int s = 0; s < nstage; s++) {
        int s2 = s + 2;
        if (s2 < nstage) {
            long long kw = (long long)s2 << 3;
            int nb = s2 % 3;
            uint32_t ao = nb * 6144, bo = nb * 4352;
            CPA(bAh + ao + dA * 4, ApH + kw, szA);
            CPA(bAl + ao + dA * 4, ApL + kw, szA);
            CPA(bBh + bo + dB * 4, BpH + kw * N, 16);
            CPA(bBl + bo + dB * 4, BpL + kw * N, 16);
            CPC();
            CPW(2);
        } else if (s + 1 < nstage) {
            CPW(1);
        } else {
            CPW(0);
        }
        __syncthreads();

        int cb = s % 3;
        const uint32_t* cAh = sAh + cb * 1536;
        const uint32_t* cAl = sAl + cb * 1536;
        const uint32_t* cBh = sBh + cb * 1088;
        const uint32_t* cBl = sBl + cb * 1088;

        uint32_t ah[4][4], al[4][4];
        #pragma unroll
        for (int mt = 0; mt < 4; mt++) {
            int r0 = (wm + (mt << 4) + g) * 12, r8 = r0 + 96;
            ah[mt][0] = cAh[r0 + tg];     ah[mt][1] = cAh[r8 + tg];
            ah[mt][2] = cAh[r0 + tg + 4]; ah[mt][3] = cAh[r8 + tg + 4];
            al[mt][0] = cAl[r0 + tg];     al[mt][1] = cAl[r8 + tg];
            al[mt][2] = cAl[r0 + tg + 4]; al[mt][3] = cAl[r8 + tg + 4];
        }
        #pragma unroll
        for (int nt = 0; nt < 4; nt++) {
            int nid = wn + (nt << 3) + g;
            uint32_t bh0 = cBh[tg * 136 + nid];
            uint32_t bh1 = cBh[(tg + 4) * 136 + nid];
            uint32_t bl0 = cBl[tg * 136 + nid];
            uint32_t bl1 = cBl[(tg + 4) * 136 + nid];
            #pragma unroll
            for (int mt = 0; mt < 4; mt++) {
                MMA_BF16(acc[mt][nt], ah[mt], bh0, bh1);
                MMA_BF16(acc[mt][nt], ah[mt], bl0, bl1);
                MMA_BF16(acc[mt][nt], al[mt], bh0, bh1);
            }
        }
        __syncthreads();
    }

    #pragma unroll
    for (int mt = 0; mt < 4; mt++) {
        int mbase = bm0 + wm + (mt << 4) + g;
        #pragma unroll
        for (int half = 0; half < 2; half++) {
            int m = mbase + half * 8;
            if (m >= M) continue;
            float g1v = 0.f, b1v = 0.f, g2v = 0.f, b2v = 0.f;
            if (mode >= 1) { g1v = G1[m]; b1v = Bi1[m]; }
            if (mode == 2) { g2v = G2[m]; b2v = Bi2[m]; }
            #pragma unroll
            for (int nt = 0; nt < 4; nt++) {
                float v0 = acc[mt][nt][half * 2 + 0];
                float v1 = acc[mt][nt][half * 2 + 1];
                if (mode >= 1) {
                    float t0 = v0 * g1v + b1v;
                    float t1 = v1 * g1v + b1v;
                    v0 = t0 / (1.f + expf(-t0));
                    v1 = t1 / (1.f + expf(-t1));
                    if (mode == 2) {
                        float u0 = v0 * g2v + b2v, u1 = v1 * g2v + b2v;
                        v0 = u0 > 0.f ? u0 : 0.f;
                        v1 = u1 > 0.f ? u1 : 0.f;
                    }
                }
                int n = bn0 + wn + (nt << 3) + 2 * tg;
                *(float2*)&C[(long long)m * N + n] = make_float2(v0, v1);
            }
        }
    }
}

// ---------------- host ----------------
extern "C" void kernel_launch(void* const* d_in, const int* in_sizes, int n_in,
                              void* d_out, int out_size) {
    const float* x     = (const float*)d_in[0];
    const float* w_gw  = (const float*)d_in[1];
    const float* gg    = (const float*)d_in[2];
    const float* bg    = (const float*)d_in[3];
    const float* w_fm  = (const float*)d_in[4];
    const float* gfm   = (const float*)d_in[5];
    const float* bfm   = (const float*)d_in[6];
    const float* w_cv2 = (const float*)d_in[7];
    const float* gcv   = (const float*)d_in[8];
    const float* bcv   = (const float*)d_in[9];
    const float* w_gf  = (const float*)d_in[10];
    const float* ggf   = (const float*)d_in[11];
    const float* bgf   = (const float*)d_in[12];
    const float* ggf2  = (const float*)d_in[13];
    const float* bgf2  = (const float*)d_in[14];
    const float* w_out = (const float*)d_in[15];
    float* out = (float*)d_out;

    float *p_w0, *p_X1, *p_weight, *p_f;
    uint32_t *p_spdPh, *p_spdPl, *p_poolAh, *p_poolAl, *p_catPh, *p_catPl;
    uint32_t *p_mpPh, *p_mpPl, *p_colPh, *p_colPl, *p_wdPh, *p_wdPl, *p_twBh, *p_twBl;
    uint32_t *p_wgwh, *p_wgwl, *p_wfmh, *p_wfml, *p_wcvh, *p_wcvl, *p_wgfh, *p_wgfl, *p_wouth, *p_woutl;
    cudaGetSymbolAddress((void**)&p_w0,     g_w0);
    cudaGetSymbolAddress((void**)&p_X1,     g_X1);
    cudaGetSymbolAddress((void**)&p_weight, g_weight);
    cudaGetSymbolAddress((void**)&p_f,      g_f);
    cudaGetSymbolAddress((void**)&p_spdPh,  g_spdPh);  cudaGetSymbolAddress((void**)&p_spdPl,  g_spdPl);
    cudaGetSymbolAddress((void**)&p_poolAh, g_poolAh); cudaGetSymbolAddress((void**)&p_poolAl, g_poolAl);
    cudaGetSymbolAddress((void**)&p_catPh,  g_catPh);  cudaGetSymbolAddress((void**)&p_catPl,  g_catPl);
    cudaGetSymbolAddress((void**)&p_mpPh,   g_mpPh);   cudaGetSymbolAddress((void**)&p_mpPl,   g_mpPl);
    cudaGetSymbolAddress((void**)&p_colPh,  g_colPh);  cudaGetSymbolAddress((void**)&p_colPl,  g_colPl);
    cudaGetSymbolAddress((void**)&p_wdPh,   g_wdPh);   cudaGetSymbolAddress((void**)&p_wdPl,   g_wdPl);
    cudaGetSymbolAddress((void**)&p_twBh,   g_twBh);   cudaGetSymbolAddress((void**)&p_twBl,   g_twBl);
    cudaGetSymbolAddress((void**)&p_wgwh,   g_wgwh);   cudaGetSymbolAddress((void**)&p_wgwl,   g_wgwl);
    cudaGetSymbolAddress((void**)&p_wfmh,   g_wfmh);   cudaGetSymbolAddress((void**)&p_wfml,   g_wfml);
    cudaGetSymbolAddress((void**)&p_wcvh,   g_wcvh);   cudaGetSymbolAddress((void**)&p_wcvl,   g_wcvl);
    cudaGetSymbolAddress((void**)&p_wgfh,   g_wgfh);   cudaGetSymbolAddress((void**)&p_wgfl,   g_wgfl);
    cudaGetSymbolAddress((void**)&p_wouth,  g_wouth);  cudaGetSymbolAddress((void**)&p_woutl,  g_woutl);

    cudaFuncSetAttribute(bgemm_kernel, cudaFuncAttributeMaxDynamicSharedMemorySize, GSM_BYTES);
    cudaFuncSetAttribute(fft_col_kernel, cudaFuncAttributeMaxDynamicSharedMemorySize, FFT_SMEM);

    init_tw_kernel<<<64, 256>>>();
    twpack_kernel<<<32, 256>>>();
    wsplit_kernel<<<288, 256>>>(w_gw, p_wgwh, p_wgwl, 73728);
    wsplit_kernel<<<648, 256>>>(w_fm, p_wfmh, p_wfml, 165888);
    wsplit_kernel<<<162, 256>>>(w_cv2, p_wcvh, p_wcvl, 41472);
    wsplit_kernel<<<2592, 256>>>(w_gf, p_wgfh, p_wgfl, 663552);
    wsplit_kernel<<<144, 256>>>(w_out, p_wouth, p_woutl, 36864);
    spd_kernel<<<65536, 256>>>(x);

    // conv_gw: (576x256)@(256x16384) per batch, silu(bn)
    {
        dim3 g(128, 5, 8);
        bgemm_kernel<<<g, 256, GSM_BYTES>>>(p_wgwh, p_wgwl, p_spdPh, p_spdPl, p_w0,
                                 576, 16384, 256, 0LL, 2097152LL, 9437184LL,
                                 gg, bg, nullptr, nullptr, 1);
    }
    avgpool_kernel<<<73728, 256>>>();

    // row rfft: (36864x128)@(128x128) per batch
    {
        dim3 g(1, 288, 8);
        bgemm_kernel<<<g, 256, GSM_BYTES>>>(p_poolAh, p_poolAl, p_twBh, p_twBl, p_X1,
                                 36864, 128, 128, 2359296LL, 0LL, 4718592LL,
                                 nullptr, nullptr, nullptr, nullptr, 0);
    }
    fft_col_kernel<<<1152, 256, FFT_SMEM>>>();

    // conv_fm: (288x1152)@(1152x4096) per batch
    {
        dim3 g(32, 3, 8);
        bgemm_kernel<<<g, 256, GSM_BYTES>>>(p_wfmh, p_wfml, p_catPh, p_catPl, p_weight,
                                 288, 4096, 1152, 0LL, 2359296LL, 2359296LL,
                                 gfm, bfm, nullptr, nullptr, 1);
    }
    maxpool_kernel<<<18432, 256>>>();

    // conv_cv2: (288x288)@(288x4096) per batch
    {
        dim3 g(32, 3, 8);
        bgemm_kernel<<<g, 256, GSM_BYTES>>>(p_wcvh, p_wcvl, p_mpPh, p_mpPl, p_weight + 288 * 4096,
                                 288, 4096, 288, 0LL, 589824LL, 2359296LL,
                                 gcv, bcv, nullptr, nullptr, 1);
    }
    im2col_kernel<<<147456, 256>>>();

    // conv_gf: (576x2304)@(2304x4096) per batch
    {
        dim3 g(32, 5, 8);
        bgemm_kernel<<<g, 256, GSM_BYTES>>>(p_wgfh, p_wgfl, p_colPh, p_colPl, p_f,
                                 576, 4096, 2304, 0LL, 4718592LL, 2359296LL,
                                 ggf, bgf, ggf2, bgf2, 2);
    }
    softmax_wd_kernel<<<4096, 256>>>();

    // final: (128x576)@(576x4096) per batch
    {
        dim3 g(32, 1, 8);
        bgemm_kernel<<<g, 256, GSM_BYTES>>>(p_wouth, p_woutl, p_wdPh, p_wdPl, out,
                                 128, 4096, 576, 0LL, 1179648LL, 524288LL,
                                 nullptr, nullptr, nullptr, nullptr, 0);
    }
}

// round 12
// speedup vs baseline: 1.0709x; 1.0709x over previous
#include <cuda_runtime.h>
#include <cuda_bf16.h>
#include <stdint.h>
#include <math.h>

#define THREADS 256
typedef unsigned short ushort_t;

// ---------------- fp32 intermediates ----------------
__device__ float g_w0[75497472];      // (8,576,128,128)
__device__ float g_pool2[37748736];   // (8,288,128,128) x2 half fp32 (maxpool source)
__device__ float g_X1[37748736];      // (8,288,128,128)
__device__ float g_weight[18874368];  // (8,576,64,64)
__device__ float g_f[18874368];       // (8,576,64,64)
__device__ float g_tw[16384];
__device__ float g_ct[128];
__device__ float g_st[128];

// ---------------- packed bf16 hi/lo (2 k's per uint32, low16 = even k) ----------------
__device__ uint32_t g_spdPh[16777216], g_spdPl[16777216];   // B: (8,128 k2,16384)
__device__ uint32_t g_poolAh[18874368], g_poolAl[18874368]; // A rows: (8*288*128, 64 words)
__device__ uint32_t g_catPh[18874368],  g_catPl[18874368];  // B: (8,576 k2,4096)
__device__ uint32_t g_mpPh[4718592],    g_mpPl[4718592];    // B: (8,144 k2,4096)
__device__ uint32_t g_colPh[37748736],  g_colPl[37748736];  // B: (8,1152 k2,4096) k'-order
__device__ uint32_t g_wdPh[9437184],    g_wdPl[9437184];    // B: (8,288 k2,4096)
__device__ uint32_t g_twBh[8192],       g_twBl[8192];       // B: (64 k2,128)
__device__ uint32_t g_wgwh[73728],  g_wgwl[73728];          // A 576x128w
__device__ uint32_t g_wfmh[165888], g_wfml[165888];         // A 288x576w
__device__ uint32_t g_wcvh[41472],  g_wcvl[41472];          // A 288x144w
__device__ uint32_t g_wgfh[663552], g_wgfl[663552];         // A 576x1152w (k'-order)
__device__ uint32_t g_wouth[36864], g_woutl[36864];         // A 128x288w

__device__ __forceinline__ void split2(float a, float b, uint32_t& hw, uint32_t& lw) {
    __nv_bfloat16 ah = __float2bfloat16(a), bh = __float2bfloat16(b);
    __nv_bfloat16 al = __float2bfloat16(a - __bfloat162float(ah));
    __nv_bfloat16 bl = __float2bfloat16(b - __bfloat162float(bh));
    hw = (uint32_t)*(ushort_t*)&ah | ((uint32_t)*(ushort_t*)&bh << 16);
    lw = (uint32_t)*(ushort_t*)&al | ((uint32_t)*(ushort_t*)&bl << 16);
}

__global__ void init_tw_kernel() {
    int i = blockIdx.x * blockDim.x + threadIdx.x;
    const double TWO_PI = 6.283185307179586476925286766559;
    if (i < 16384) {
        int q = i >> 7, v = i & 127;
        if (v < 64)
            g_tw[i] = (float)cos(TWO_PI * (double)((q * v) & 127) / 128.0);
        else
            g_tw[i] = (float)(-sin(TWO_PI * (double)((q * (v - 64)) & 127) / 128.0));
    }
    if (i < 128) {
        g_ct[i] = (float)cos(TWO_PI * (double)i / 128.0);
        g_st[i] = (float)sin(TWO_PI * (double)i / 128.0);
    }
}

__global__ void twpack_kernel() {
    int i = blockIdx.x * blockDim.x + threadIdx.x;
    if (i >= 8192) return;
    int k2 = i >> 7, v = i & 127;
    split2(g_tw[(2 * k2) * 128 + v], g_tw[(2 * k2 + 1) * 128 + v], g_twBh[i], g_twBl[i]);
}

__global__ void wsplit_kernel(const float* __restrict__ W, uint32_t* __restrict__ Wh,
                              uint32_t* __restrict__ Wl, int nwords) {
    int i = blockIdx.x * THREADS + threadIdx.x;
    if (i >= nwords) return;
    split2(W[2 * i], W[2 * i + 1], Wh[i], Wl[i]);
}

// w_gf split in permuted k' = t*256 + ic order (word = (t, ic-pair))
__global__ void wsplit_gf_kernel(const float* __restrict__ W) {
    int i = blockIdx.x * THREADS + threadIdx.x;
    if (i >= 663552) return;
    int w = i % 1152, m = i / 1152;
    int t = w >> 7, ic2 = w & 127;
    const float* p = W + (size_t)m * 2304 + (size_t)(2 * ic2) * 9 + t;
    split2(p[0], p[9], g_wgfh[i], g_wgfl[i]);
}

// space-to-depth: channel pair per thread -> full-word packed stores
__global__ void spd_kernel(const float* __restrict__ x) {
    int i = blockIdx.x * THREADS + threadIdx.x;
    if (i >= 16777216) return;
    int n = i & 16383, s2 = (i >> 14) & 127, b = i >> 21;
    int q = n & 127, p = n >> 7;
    int s0 = s2 << 1;
    int quad = s0 >> 6, c = s0 & 63;
    int r  = 2 * p + (quad & 1);
    int cc = 2 * q + (quad >> 1);
    const float* xp = x + ((size_t)(b * 64 + c) * 256 + r) * 256 + cc;
    float v0 = xp[0];
    float v1 = xp[65536];
    uint32_t h, l;
    split2(v0, v1, h, l);
    size_t w = ((size_t)(b * 128 + s2) << 14) + n;
    g_spdPh[w] = h; g_spdPl[w] = l;
}

__global__ void avgpool_kernel() {
    int i = blockIdx.x * THREADS + threadIdx.x;
    if (i >= 18874368) return;
    int q4 = (i & 31) << 2;
    int p  = (i >> 5) & 127;
    int cb = i >> 12;
    int ch = cb % 576, b = cb / 576;
    float4 o = make_float4(0.f, 0.f, 0.f, 0.f);
    if (p < 127) {
        const float* s = g_w0 + ((size_t)cb << 14);
        int ofs = (p << 7) + q4;
        float4 a = *(const float4*)(s + ofs);
        float4 bb = *(const float4*)(s + ofs + 128);
        o.x = 0.25f * (a.x + a.y + bb.x + bb.y);
        o.y = 0.25f * (a.y + a.z + bb.y + bb.z);
        o.z = 0.25f * (a.z + a.w + bb.z + bb.w);
        if (q4 < 124) {
            float a4 = s[ofs + 4], b4 = s[ofs + 132];
            o.w = 0.25f * (a.w + a4 + bb.w + b4);
        }
    }
    if (ch < 288) {
        uint32_t h0, l0, h1, l1;
        split2(o.x, o.y, h0, l0);
        split2(o.z, o.w, h1, l1);
        size_t wb = ((size_t)(b * 288 + ch) << 13) + (p << 6) + (q4 >> 1);
        g_poolAh[wb] = h0; g_poolAh[wb + 1] = h1;
        g_poolAl[wb] = l0; g_poolAl[wb + 1] = l1;
    } else {
        *(float4*)(g_pool2 + ((size_t)(b * 288 + ch - 288) << 14) + (p << 7) + q4) = o;
    }
}

// maxpool: channel pair per thread -> full-word stores
__global__ void maxpool_kernel() {
    int i = blockIdx.x * THREADS + threadIdx.x;
    if (i >= 4718592) return;
    int n = i & 4095;
    int v = n & 63, u = n >> 6;
    int cb = i >> 12;
    int c2 = cb % 144, b = cb / 144;
    const float* sA = g_pool2 + ((size_t)(b * 288 + 2 * c2) << 14);
    const float* sB = sA + 16384;
    int r0 = max(2 * u - 1, 0), r1 = min(2 * u + 1, 126);
    int q0 = max(2 * v - 1, 0), q1 = min(2 * v + 1, 126);
    float m0 = -3.4e38f, m1 = -3.4e38f;
    for (int r = r0; r <= r1; r++)
        for (int cc = q0; cc <= q1; cc++) {
            int o = (r << 7) + cc;
            m0 = fmaxf(m0, sA[o]);
            m1 = fmaxf(m1, sB[o]);
        }
    uint32_t h, l;
    split2(m0, m1, h, l);
    size_t w = ((size_t)(b * 144 + c2) << 12) + n;
    g_mpPh[w] = h; g_mpPl[w] = l;
}

// im2col in k'-order: pure full-word copy from packed spd (k2' = t*128 + ic2)
__global__ void im2col_kernel() {
    int i = blockIdx.x * THREADS + threadIdx.x;
    if (i >= 37748736) return;
    int n = i & 4095;
    int v = n & 63, u = n >> 6;
    int kb = i >> 12;
    int k2 = kb % 1152, b = kb / 1152;
    int t = k2 >> 7, ic2 = k2 & 127;
    int di = t / 3, dj = t - di * 3;
    int r  = 2 * u + di - 1;
    int cc = 2 * v + dj - 1;
    uint32_t hw = 0, lw = 0;
    if ((unsigned)r < 128u && (unsigned)cc < 128u) {
        size_t idx = ((size_t)(b * 128 + ic2) << 14) + (r << 7) + cc;
        hw = g_spdPh[idx]; lw = g_spdPl[idx];
    }
    size_t w = ((size_t)(b * 1152 + k2) << 12) + n;
    g_colPh[w] = hw; g_colPl[w] = lw;
}

// column FFT radix-4, float2 LDS, TWO channels per block, full-word packed stores
#define FFT_SMEM ((8192 + 128) * 8)
__global__ __launch_bounds__(256) void fft_col_kernel() {
    extern __shared__ float2 ds[];
    float2* Xs0 = ds;
    float2* Xs1 = ds + 4096;
    float2* tws = ds + 8192;
    int blk = blockIdx.x;
    int b = blk / 144, j = blk % 144;
    int tid = threadIdx.x;
    if (tid < 128) tws[tid] = make_float2(g_ct[tid], g_st[tid]);
    const float* X1a = g_X1 + (size_t)(b * 288 + 2 * j) * 16384;
    const float* X1b = X1a + 16384;
    size_t wLRe = ((size_t)(b * 576) + j) << 12;
    size_t wLIm = wLRe + ((size_t)144 << 12);
    size_t wHRe = wLRe + ((size_t)288 << 12);
    size_t wHIm = wLRe + ((size_t)432 << 12);
    for (int half = 0; half < 2; half++) {
        int v0 = half << 5;
        __syncthreads();
        for (int e = tid; e < 4096; e += 256) {
            int p = e >> 5, v = e & 31;
            Xs0[(p << 5) + v] = make_float2(X1a[(p << 7) + v0 + v], X1a[(p << 7) + 64 + v0 + v]);
            Xs1[(p << 5) + v] = make_float2(X1b[(p << 7) + v0 + v], X1b[(p << 7) + 64 + v0 + v]);
        }
        __syncthreads();
        for (int r = 0; r < 4; r++) {
            int item = (r << 8) + tid;
            int u = item >> 5, v = item & 31;
            float a0r=0.f,a0i=0.f,a1r=0.f,a1i=0.f,a2r=0.f,a2i=0.f,a3r=0.f,a3i=0.f;
            float b0r=0.f,b0i=0.f,b1r=0.f,b1i=0.f,b2r=0.f,b2i=0.f,b3r=0.f,b3i=0.f;
            int u1 = u, u2 = (2 * u) & 127, u3 = (3 * u) & 127, u4 = (4 * u) & 127;
            int idx = 0;
            #pragma unroll 4
            for (int p = 0; p < 128; p += 4) {
                {
                    float2 t = tws[idx];
                    float2 xa = Xs0[(p << 5) + v], xb = Xs1[(p << 5) + v];
                    a0r = fmaf(xa.x, t.x, a0r); a0r = fmaf(xa.y, t.y, a0r);
                    a0i = fmaf(xa.y, t.x, a0i); a0i = fmaf(-xa.x, t.y, a0i);
                    b0r = fmaf(xb.x, t.x, b0r); b0r = fmaf(xb.y, t.y, b0r);
                    b0i = fmaf(xb.y, t.x, b0i); b0i = fmaf(-xb.x, t.y, b0i);
                }
                {
                    int id = (idx + u1) & 127;
                    float2 t = tws[id];
                    float2 xa = Xs0[((p + 1) << 5) + v], xb = Xs1[((p + 1) << 5) + v];
                    a1r = fmaf(xa.x, t.x, a1r); a1r = fmaf(xa.y, t.y, a1r);
                    a1i = fmaf(xa.y, t.x, a1i); a1i = fmaf(-xa.x, t.y, a1i);
                    b1r = fmaf(xb.x, t.x, b1r); b1r = fmaf(xb.y, t.y, b1r);
                    b1i = fmaf(xb.y, t.x, b1i); b1i = fmaf(-xb.x, t.y, b1i);
                }
                {
                    int id = (idx + u2) & 127;
                    float2 t = tws[id];
                    float2 xa = Xs0[((p + 2) << 5) + v], xb = Xs1[((p + 2) << 5) + v];
                    a2r = fmaf(xa.x, t.x, a2r); a2r = fmaf(xa.y, t.y, a2r);
                    a2i = fmaf(xa.y, t.x, a2i); a2i = fmaf(-xa.x, t.y, a2i);
                    b2r = fmaf(xb.x, t.x, b2r); b2r = fmaf(xb.y, t.y, b2r);
                    b2i = fmaf(xb.y, t.x, b2i); b2i = fmaf(-xb.x, t.y, b2i);
                }
                {
                    int id = (idx + u3) & 127;
                    float2 t = tws[id];
                    float2 xa = Xs0[((p + 3) << 5) + v], xb = Xs1[((p + 3) << 5) + v];
                    a3r = fmaf(xa.x, t.x, a3r); a3r = fmaf(xa.y, t.y, a3r);
                    a3i = fmaf(xa.y, t.x, a3i); a3i = fmaf(-xa.x, t.y, a3i);
                    b3r = fmaf(xb.x, t.x, b3r); b3r = fmaf(xb.y, t.y, b3r);
                    b3i = fmaf(xb.y, t.x, b3i); b3i = fmaf(-xb.x, t.y, b3i);
                }
                idx = (idx + u4) & 127;
            }
            float ArA = a0r + a2r, AiA = a0i + a2i, ArB = a0r - a2r, AiB = a0i - a2i;
            float ArC = a1r + a3r, AiC = a1i + a3i, ArD = a1r - a3r, AiD = a1i - a3i;
            float BrA = b0r + b2r, BiA = b0i + b2i, BrB = b0r - b2r, BiB = b0i - b2i;
            float BrC = b1r + b3r, BiC = b1i + b3i, BrD = b1r - b3r, BiD = b1i - b3i;
            int vv = v0 + v;
            size_t off_u   = (size_t)((u << 6) + vv);
            size_t off_u32 = (size_t)(((u + 32) << 6) + vv);
            uint32_t h, l;
            split2(ArA + ArC, BrA + BrC, h, l); g_catPh[wLRe + off_u]   = h; g_catPl[wLRe + off_u]   = l;
            split2(AiA + AiC, BiA + BiC, h, l); g_catPh[wLIm + off_u]   = h; g_catPl[wLIm + off_u]   = l;
            split2(ArB + AiD, BrB + BiD, h, l); g_catPh[wLRe + off_u32] = h; g_catPl[wLRe + off_u32] = l;
            split2(AiB - ArD, BiB - BrD, h, l); g_catPh[wLIm + off_u32] = h; g_catPl[wLIm + off_u32] = l;
            split2(ArA - ArC, BrA - BrC, h, l); g_catPh[wHRe + off_u]   = h; g_catPl[wHRe + off_u]   = l;
            split2(AiA - AiC, BiA - BiC, h, l); g_catPh[wHIm + off_u]   = h; g_catPl[wHIm + off_u]   = l;
            split2(ArB - AiD, BrB - BiD, h, l); g_catPh[wHRe + off_u32] = h; g_catPl[wHRe + off_u32] = l;
            split2(AiB + ArD, BiB + BrD, h, l); g_catPh[wHIm + off_u32] = h; g_catPl[wHIm + off_u32] = l;
        }
    }
}

// softmax+gate: channel pair per thread -> full-word stores
__global__ void softmax_wd_kernel() {
    int i = blockIdx.x * THREADS + threadIdx.x;
    if (i >= 1048576) return;
    int n = i & 4095;
    int jb = i >> 12;
    int j = jb & 31, b = jb >> 5;
    float flat[18];
    #pragma unroll
    for (int e = 0; e < 2; e++) {
        int c = 2 * j + e;
        size_t base = (size_t)(b * 576 + c * 9) * 4096 + n;
        float w[9];
        float mx = -3.4e38f;
        #pragma unroll
        for (int t = 0; t < 9; t++) { w[t] = g_weight[base + t * 4096]; mx = fmaxf(mx, w[t]); }
        float sum = 0.f;
        #pragma unroll
        for (int t = 0; t < 9; t++) { w[t] = expf(w[t] - mx); sum += w[t]; }
        float inv = 1.f / sum;
        #pragma unroll
        for (int t = 0; t < 9; t++)
            flat[e * 9 + t] = g_f[base + t * 4096] * w[t] * inv;
    }
    #pragma unroll
    for (int w = 0; w < 9; w++) {
        uint32_t h, l;
        split2(flat[2 * w], flat[2 * w + 1], h, l);
        size_t idx = ((size_t)(b * 288 + 9 * j + w) << 12) + n;
        g_wdPh[idx] = h; g_wdPl[idx] = l;
    }
}

// ---------------- tensor-core GEMM, pre-split packed bf16, 3-stage cp.async ----------------
#define MMA_BF16(d, a, b0_, b1_) \
    asm volatile("mma.sync.aligned.m16n8k16.row.col.f32.bf16.bf16.f32 " \
        "{%0,%1,%2,%3},{%4,%5,%6,%7},{%8,%9},{%0,%1,%2,%3};" \
        : "+f"(d[0]), "+f"(d[1]), "+f"(d[2]), "+f"(d[3]) \
        : "r"(a[0]), "r"(a[1]), "r"(a[2]), "r"(a[3]), "r"(b0_), "r"(b1_))

#define CPA(dst, src, sz) asm volatile("cp.async.cg.shared.global [%0], [%1], 16, %2;" \
        :: "r"(dst), "l"(src), "r"(sz))
#define CPC() asm volatile("cp.async.commit_group;")
#define CPW(n) asm volatile("cp.async.wait_group %0;" :: "n"(n))

__device__ __forceinline__ uint32_t smaddr(const void* p) {
    return (uint32_t)__cvta_generic_to_shared(p);
}

#define GSM_BYTES 62976
__global__ __launch_bounds__(256, 1) void bgemm_kernel(
    const uint32_t* __restrict__ Ah, const uint32_t* __restrict__ Al,
    const uint32_t* __restrict__ Bh, const uint32_t* __restrict__ Bl,
    float* __restrict__ C, int M, int N, int K,
    long long sA, long long sB, long long sC,
    const float* __restrict__ G1, const float* __restrict__ Bi1,
    const float* __restrict__ G2, const float* __restrict__ Bi2, int mode)
{
    extern __shared__ uint32_t sm[];
    uint32_t* sAh = sm;              // [3][1536]
    uint32_t* sAl = sm + 4608;       // [3][1536]
    uint32_t* sBh = sm + 9216;       // [3][1088]
    uint32_t* sBl = sm + 12480;      // [3][1088]

    int tid = threadIdx.x;
    int bn0 = blockIdx.x << 7, bm0 = blockIdx.y << 7;
    int Kw = K >> 1;
    Ah += (long long)blockIdx.z * sA;  Al += (long long)blockIdx.z * sA;
    Bh += (long long)blockIdx.z * sB;  Bl += (long long)blockIdx.z * sB;
    C  += (long long)blockIdx.z * sC;

    int aRow = tid >> 1, wofs = (tid & 1) << 2;
    bool aOk = (bm0 + aRow) < M;
    uint32_t szA = aOk ? 16u : 0u;
    const uint32_t* ApH = Ah + (long long)(aOk ? (bm0 + aRow) : 0) * Kw + wofs;
    const uint32_t* ApL = Al + (long long)(aOk ? (bm0 + aRow) : 0) * Kw + wofs;
    int bK2 = tid >> 5, bN0 = (tid & 31) << 2;
    const uint32_t* BpH = Bh + (long long)bK2 * N + bn0 + bN0;
    const uint32_t* BpL = Bl + (long long)bK2 * N + bn0 + bN0;

    uint32_t dA = (uint32_t)(aRow * 12 + wofs);
    uint32_t dB = (uint32_t)(bK2 * 136 + bN0);
    uint32_t bAh = smaddr(sAh), bAl = smaddr(sAl);
    uint32_t bBh = smaddr(sBh), bBl = smaddr(sBl);

    int wid = tid >> 5, lane = tid & 31;
    int wm = (wid >> 2) << 6, wn = (wid & 3) << 5;
    int g = lane >> 2, tg = lane & 3;

    float acc[4][4][4];
    #pragma unroll
    for (int i = 0; i < 4; i++)
        #pragma unroll
        for (int j = 0; j < 4; j++)
            #pragma unroll
            for (int r = 0; r < 4; r++) acc[i][j][r] = 0.f;

    int nstage = K >> 4;

    #pragma unroll
    for (int t = 0; t < 2; t++) {
        if (t < nstage) {
            long long kw = (long long)t << 3;
            uint32_t ao = t * 6144, bo = t * 4352;
            CPA(bAh + ao + dA * 4, ApH + kw, szA);
            CPA(bAl + ao + dA * 4, ApL + kw, szA);
            CPA(bBh + bo + dB * 4, BpH + kw * N, 16);
            CPA(bBl + bo + dB * 4, BpL + kw * N, 16);
            CPC();
        }
    }

    for (int s = 0; s < nstage; s++) {
        int s2 = s + 2;
        if (s2 < nstage) {
            long long kw = (long long)s2 << 3;
            int nb = s2 % 3;
            uint32_t ao = nb * 6144, bo = nb * 4352;
            CPA(bAh + ao + dA * 4, ApH + kw, szA);
            CPA(bAl + ao + dA * 4, ApL + kw, szA);
            CPA(bBh + bo + dB * 4, BpH + kw * N, 16);
            CPA(bBl + bo + dB * 4, BpL + kw * N, 16);
            CPC();
            CPW(2);
        } else if (s + 1 < nstage) {
            CPW(1);
        } else {
            CPW(0);
        }
        __syncthreads();

        int cb = s % 3;
        const uint32_t* cAh = sAh + cb * 1536;
        const uint32_t* cAl = sAl + cb * 1536;
        const uint32_t* cBh = sBh + cb * 1088;
        const uint32_t* cBl = sBl + cb * 1088;

        uint32_t ah[4][4], al[4][4];
        #pragma unroll
        for (int mt = 0; mt < 4; mt++) {
            int r0 = (wm + (mt << 4) + g) * 12, r8 = r0 + 96;
            ah[mt][0] = cAh[r0 + tg];     ah[mt][1] = cAh[r8 + tg];
            ah[mt][2] = cAh[r0 + tg + 4]; ah[mt][3] = cAh[r8 + tg + 4];
            al[mt][0] = cAl[r0 + tg];     al[mt][1] = cAl[r8 + tg];
            al[mt][2] = cAl[r0 + tg + 4]; al[mt][3] = cAl[r8 + tg + 4];
        }
        #pragma unroll
        for (int nt = 0; nt < 4; nt++) {
            int nid = wn + (nt << 3) + g;
            uint32_t bh0 = cBh[tg * 136 + nid];
            uint32_t bh1 = cBh[(tg + 4) * 136 + nid];
            uint32_t bl0 = cBl[tg * 136 + nid];
            uint32_t bl1 = cBl[(tg + 4) * 136 + nid];
            #pragma unroll
            for (int mt = 0; mt < 4; mt++) {
                MMA_BF16(acc[mt][nt], ah[mt], bh0, bh1);
                MMA_BF16(acc[mt][nt], ah[mt], bl0, bl1);
                MMA_BF16(acc[mt][nt], al[mt], bh0, bh1);
            }
        }
        __syncthreads();
    }

    #pragma unroll
    for (int mt = 0; mt < 4; mt++) {
        int mbase = bm0 + wm + (mt << 4) + g;
        #pragma unroll
        for (int half = 0; half < 2; half++) {
            int m = mbase + half * 8;
            if (m >= M) continue;
            float g1v = 0.f, b1v = 0.f, g2v = 0.f, b2v = 0.f;
            if (mode >= 1) { g1v = G1[m]; b1v = Bi1[m]; }
            if (mode == 2) { g2v = G2[m]; b2v = Bi2[m]; }
            #pragma unroll
            for (int nt = 0; nt < 4; nt++) {
                float v0 = acc[mt][nt][half * 2 + 0];
                float v1 = acc[mt][nt][half * 2 + 1];
                if (mode >= 1) {
                    float t0 = v0 * g1v + b1v;
                    float t1 = v1 * g1v + b1v;
                    v0 = t0 / (1.f + expf(-t0));
                    v1 = t1 / (1.f + expf(-t1));
                    if (mode == 2) {
                        float u0 = v0 * g2v + b2v, u1 = v1 * g2v + b2v;
                        v0 = u0 > 0.f ? u0 : 0.f;
                        v1 = u1 > 0.f ? u1 : 0.f;
                    }
                }
                int n = bn0 + wn + (nt << 3) + 2 * tg;
                *(float2*)&C[(long long)m * N + n] = make_float2(v0, v1);
            }
        }
    }
}

// ---------------- host ----------------
extern "C" void kernel_launch(void* const* d_in, const int* in_sizes, int n_in,
                              void* d_out, int out_size) {
    const float* x     = (const float*)d_in[0];
    const float* w_gw  = (const float*)d_in[1];
    const float* gg    = (const float*)d_in[2];
    const float* bg    = (const float*)d_in[3];
    const float* w_fm  = (const float*)d_in[4];
    const float* gfm   = (const float*)d_in[5];
    const float* bfm   = (const float*)d_in[6];
    const float* w_cv2 = (const float*)d_in[7];
    const float* gcv   = (const float*)d_in[8];
    const float* bcv   = (const float*)d_in[9];
    const float* w_gf  = (const float*)d_in[10];
    const float* ggf   = (const float*)d_in[11];
    const float* bgf   = (const float*)d_in[12];
    const float* ggf2  = (const float*)d_in[13];
    const float* bgf2  = (const float*)d_in[14];
    const float* w_out = (const float*)d_in[15];
    float* out = (float*)d_out;

    float *p_w0, *p_X1, *p_weight, *p_f;
    uint32_t *p_spdPh, *p_spdPl, *p_poolAh, *p_poolAl, *p_catPh, *p_catPl;
    uint32_t *p_mpPh, *p_mpPl, *p_colPh, *p_colPl, *p_wdPh, *p_wdPl, *p_twBh, *p_twBl;
    uint32_t *p_wgwh, *p_wgwl, *p_wfmh, *p_wfml, *p_wcvh, *p_wcvl, *p_wgfh, *p_wgfl, *p_wouth, *p_woutl;
    cudaGetSymbolAddress((void**)&p_w0,     g_w0);
    cudaGetSymbolAddress((void**)&p_X1,     g_X1);
    cudaGetSymbolAddress((void**)&p_weight, g_weight);
    cudaGetSymbolAddress((void**)&p_f,      g_f);
    cudaGetSymbolAddress((void**)&p_spdPh,  g_spdPh);  cudaGetSymbolAddress((void**)&p_spdPl,  g_spdPl);
    cudaGetSymbolAddress((void**)&p_poolAh, g_poolAh); cudaGetSymbolAddress((void**)&p_poolAl, g_poolAl);
    cudaGetSymbolAddress((void**)&p_catPh,  g_catPh);  cudaGetSymbolAddress((void**)&p_catPl,  g_catPl);
    cudaGetSymbolAddress((void**)&p_mpPh,   g_mpPh);   cudaGetSymbolAddress((void**)&p_mpPl,   g_mpPl);
    cudaGetSymbolAddress((void**)&p_colPh,  g_colPh);  cudaGetSymbolAddress((void**)&p_colPl,  g_colPl);
    cudaGetSymbolAddress((void**)&p_wdPh,   g_wdPh);   cudaGetSymbolAddress((void**)&p_wdPl,   g_wdPl);
    cudaGetSymbolAddress((void**)&p_twBh,   g_twBh);   cudaGetSymbolAddress((void**)&p_twBl,   g_twBl);
    cudaGetSymbolAddress((void**)&p_wgwh,   g_wgwh);   cudaGetSymbolAddress((void**)&p_wgwl,   g_wgwl);
    cudaGetSymbolAddress((void**)&p_wfmh,   g_wfmh);   cudaGetSymbolAddress((void**)&p_wfml,   g_wfml);
    cudaGetSymbolAddress((void**)&p_wcvh,   g_wcvh);   cudaGetSymbolAddress((void**)&p_wcvl,   g_wcvl);
    cudaGetSymbolAddress((void**)&p_wgfh,   g_wgfh);   cudaGetSymbolAddress((void**)&p_wgfl,   g_wgfl);
    cudaGetSymbolAddress((void**)&p_wouth,  g_wouth);  cudaGetSymbolAddress((void**)&p_woutl,  g_woutl);

    cudaFuncSetAttribute(bgemm_kernel, cudaFuncAttributeMaxDynamicSharedMemorySize, GSM_BYTES);
    cudaFuncSetAttribute(fft_col_kernel, cudaFuncAttributeMaxDynamicSharedMemorySize, FFT_SMEM);

    init_tw_kernel<<<64, 256>>>();
    twpack_kernel<<<32, 256>>>();
    wsplit_kernel<<<288, 256>>>(w_gw, p_wgwh, p_wgwl, 73728);
    wsplit_kernel<<<648, 256>>>(w_fm, p_wfmh, p_wfml, 165888);
    wsplit_kernel<<<162, 256>>>(w_cv2, p_wcvh, p_wcvl, 41472);
    wsplit_gf_kernel<<<2592, 256>>>(w_gf);
    wsplit_kernel<<<144, 256>>>(w_out, p_wouth, p_woutl, 36864);
    spd_kernel<<<65536, 256>>>(x);

    // conv_gw: (576x256)@(256x16384) per batch, silu(bn)
    {
        dim3 g(128, 5, 8);
        bgemm_kernel<<<g, 256, GSM_BYTES>>>(p_wgwh, p_wgwl, p_spdPh, p_spdPl, p_w0,
                                 576, 16384, 256, 0LL, 2097152LL, 9437184LL,
                                 gg, bg, nullptr, nullptr, 1);
    }
    avgpool_kernel<<<73728, 256>>>();

    // row rfft: (36864x128)@(128x128) per batch
    {
        dim3 g(1, 288, 8);
        bgemm_kernel<<<g, 256, GSM_BYTES>>>(p_poolAh, p_poolAl, p_twBh, p_twBl, p_X1,
                                 36864, 128, 128, 2359296LL, 0LL, 4718592LL,
                                 nullptr, nullptr, nullptr, nullptr, 0);
    }
    fft_col_kernel<<<1152, 256, FFT_SMEM>>>();

    // conv_fm: (288x1152)@(1152x4096) per batch
    {
        dim3 g(32, 3, 8);
        bgemm_kernel<<<g, 256, GSM_BYTES>>>(p_wfmh, p_wfml, p_catPh, p_catPl, p_weight,
                                 288, 4096, 1152, 0LL, 2359296LL, 2359296LL,
                                 gfm, bfm, nullptr, nullptr, 1);
    }
    maxpool_kernel<<<18432, 256>>>();

    // conv_cv2: (288x288)@(288x4096) per batch
    {
        dim3 g(32, 3, 8);
        bgemm_kernel<<<g, 256, GSM_BYTES>>>(p_wcvh, p_wcvl, p_mpPh, p_mpPl, p_weight + 288 * 4096,
                                 288, 4096, 288, 0LL, 589824LL, 2359296LL,
                                 gcv, bcv, nullptr, nullptr, 1);
    }
    im2col_kernel<<<147456, 256>>>();

    // conv_gf: (576x2304)@(2304x4096) per batch, K in k'-order on both sides
    {
        dim3 g(32, 5, 8);
        bgemm_kernel<<<g, 256, GSM_BYTES>>>(p_wgfh, p_wgfl, p_colPh, p_colPl, p_f,
                                 576, 4096, 2304, 0LL, 4718592LL, 2359296LL,
                                 ggf, bgf, ggf2, bgf2, 2);
    }
    softmax_wd_kernel<<<4096, 256>>>();

    // final: (128x576)@(576x4096) per batch
    {
        dim3 g(32, 1, 8);
        bgemm_kernel<<<g, 256, GSM_BYTES>>>(p_wouth, p_woutl, p_wdPh, p_wdPl, out,
                                 128, 4096, 576, 0LL, 1179648LL, 524288LL,
                                 nullptr, nullptr, nullptr, nullptr, 0);
    }
}